// round 15
// baseline (speedup 1.0000x reference)
#include <cuda_runtime.h>
#include <cuda_fp16.h>
#include <stdint.h>

// Problem constants (fixed shapes from reference)
#define M_DIM 32
#define N_DIM 11008
#define K_DIM 4096

// Harness promotes unsupported dtypes: float16 -> float32, int8 -> int32.
// x fp32 [32,4096], qweight int32 [11008,4096], scales fp32 [11008],
// bias fp32 [11008], out fp32 [32,11008] (values fp16-rounded like reference).

#define N_TILE   64                 // output channels per CTA
#define N_TILES  (N_DIM / N_TILE)   // 172
#define SPLIT_K  8                  // grid (172, 8) = 1376 CTAs (measured-best)
#define K_PER_SPLIT (K_DIM / SPLIT_K)      // 512
#define K_CHUNK  64                 // K elements (int32) staged per stage = 256 B/row
#define N_WARPS  8
#define THREADS  (N_WARPS * 32)
#define N_CHUNKS (K_PER_SPLIT / K_CHUNK)   // 8
#define KSTEPS   (K_CHUNK / 16)     // 4 mma k-steps per chunk

#define X_STRIDE 72                 // halves per x row in smem (64 + 8 pad)
#define W_STRIDE 72                 // int32 per w row in smem (64 data + 8 pad = 288 B)
#define W_ROW_BYTES 256             // bytes of weight data per row per chunk
#define W_TILE_BYTES (N_TILE * W_ROW_BYTES)   // 16384 per stage

#define MN (M_DIM * N_DIM)          // 352256

// Static device scratch (no allocation in kernel_launch).
__device__ float g_part[SPLIT_K * MN];   // 11.3 MB fp32 partials
__device__ int   g_cnt[N_TILES];         // arrival counters; never reset (modulo detect)

__device__ __forceinline__ uint32_t smem_addr(const void* p) {
    return (uint32_t)__cvta_generic_to_shared(p);
}

__device__ __forceinline__ void mbar_init(uint32_t mbar, uint32_t count) {
    asm volatile("mbarrier.init.shared.b64 [%0], %1;" :: "r"(mbar), "r"(count) : "memory");
}

__device__ __forceinline__ void mbar_expect_tx(uint32_t mbar, uint32_t bytes) {
    asm volatile("mbarrier.arrive.expect_tx.shared.b64 _, [%0], %1;"
                 :: "r"(mbar), "r"(bytes) : "memory");
}

__device__ __forceinline__ void mbar_wait(uint32_t mbar, uint32_t parity) {
    asm volatile(
        "{\n\t"
        ".reg .pred p;\n\t"
        "LAB_WAIT_%=:\n\t"
        "mbarrier.try_wait.parity.shared.b64 p, [%0], %1, 0x989680;\n\t"
        "@p bra LAB_DONE_%=;\n\t"
        "bra.uni LAB_WAIT_%=;\n\t"
        "LAB_DONE_%=:\n\t"
        "}"
        :: "r"(mbar), "r"(parity) : "memory");
}

// Bulk-copy (TMA path) the 64-row weight tile for K-chunk at element k0 into sw.
// One 256B bulk op per row; dst row stride 288B preserves bank-conflict-free layout.
__device__ __forceinline__ void issue_w_bulk(
    const int32_t* __restrict__ qw, int n_base, int32_t* sw, int k0, uint32_t mbar)
{
    mbar_expect_tx(mbar, W_TILE_BYTES);
    const int32_t* src = qw + (size_t)n_base * K_DIM + k0;
    uint32_t dst = smem_addr(sw);
    #pragma unroll 8
    for (int r = 0; r < N_TILE; r++) {
        asm volatile(
            "cp.async.bulk.shared::cluster.global.mbarrier::complete_tx::bytes "
            "[%0], [%1], %2, [%3];"
            :: "r"(dst + r * (W_STRIDE * 4)), "l"(src + (size_t)r * K_DIM),
               "r"(W_ROW_BYTES), "r"(mbar) : "memory");
    }
}

__device__ __forceinline__ void ldg_x(
    const float* __restrict__ x32, int k0, int tid, float4& a, float4& b)
{
    const float* src = x32 + (size_t)(tid >> 3) * K_DIM + k0 + (tid & 7) * 8;
    a = __ldg((const float4*)src);
    b = __ldg((const float4*)(src + 4));
}

__device__ __forceinline__ void sts_x(__half* sx, int tid, float4 a, float4 b)
{
    __half2 h[4];
    h[0] = __halves2half2(__float2half(a.x), __float2half(a.y));
    h[1] = __halves2half2(__float2half(a.z), __float2half(a.w));
    h[2] = __halves2half2(__float2half(b.x), __float2half(b.y));
    h[3] = __halves2half2(__float2half(b.z), __float2half(b.w));
    *reinterpret_cast<uint4*>(sx + (tid >> 3) * X_STRIDE + (tid & 7) * 8) =
        *reinterpret_cast<uint4*>(h);
}

__device__ __forceinline__ float4 ldg_cg4(const float* p) {
    float4 q;
    asm volatile("ld.global.cg.v4.f32 {%0,%1,%2,%3}, [%4];"
                 : "=f"(q.x), "=f"(q.y), "=f"(q.z), "=f"(q.w) : "l"(p));
    return q;
}

__global__ void __launch_bounds__(THREADS, 3)
qlinear_s8_kernel(const int32_t* __restrict__ qw, const float* __restrict__ x32,
                  const float* __restrict__ scales, const float* __restrict__ bias,
                  float* __restrict__ out)
{
    __shared__ __align__(16) __half   sx[2][M_DIM * X_STRIDE];   // 2 x 4608 B
    __shared__ __align__(16) int32_t  sw[2][N_TILE * W_STRIDE];  // 2 x 18432 B
    __shared__ __align__(8)  uint64_t mbar[2];                   // full-barriers per stage
    __shared__ int s_last;

    const int tid  = threadIdx.x;
    const int warp = tid >> 5;
    const int lane = tid & 31;
    const int n_base = blockIdx.x * N_TILE;
    const int split  = blockIdx.y;
    const int k_base = split * K_PER_SPLIT;

    float acc[2][4] = {{0.f, 0.f, 0.f, 0.f}, {0.f, 0.f, 0.f, 0.f}};

    // B operand per-thread source: row (n) = warp*8 + lane/4, k offset (lane%4)*2.
    const int o_row = warp * 8 + (lane >> 2);
    const int kb    = (lane & 3) * 2;

    const uint32_t mb0 = smem_addr(&mbar[0]);
    const uint32_t mb1 = smem_addr(&mbar[1]);

    // Prologue: init mbarriers, then stage chunk 0.
    if (tid == 0) {
        mbar_init(mb0, 1);
        mbar_init(mb1, 1);
        asm volatile("fence.proxy.async.shared::cta;" ::: "memory");
    }
    __syncthreads();   // mbarrier init visible to all (and to async proxy)

    if (tid == 0) issue_w_bulk(qw, n_base, sw[0], k_base, mb0);
    {
        float4 xa, xb;
        ldg_x(x32, k_base, tid, xa, xb);
        sts_x(sx[0], tid, xa, xb);
    }
    __syncthreads();   // sx[0] visible before chunk-0 compute

    #pragma unroll 1
    for (int ch = 0; ch < N_CHUNKS; ch++) {
        const int buf = ch & 1;
        float4 xa, xb;
        const bool has_next = (ch + 1 < N_CHUNKS);

        // Produce chunk ch+1 into the other stage. Safe: that stage's previous
        // consumers finished before the trailing __syncthreads of iter ch-1.
        if (has_next) {
            if (tid == 0)
                issue_w_bulk(qw, n_base, sw[buf ^ 1], k_base + (ch + 1) * K_CHUNK,
                             buf ? mb0 : mb1);
            ldg_x(x32, k_base + (ch + 1) * K_CHUNK, tid, xa, xb);   // hidden by MMAs
        }

        // Wait for chunk ch's weights (production index ch>>1 on this stage).
        mbar_wait(buf ? mb1 : mb0, (ch >> 1) & 1);

        const __half*   xs = sx[buf];
        const int32_t*  ws = &sw[buf][o_row * W_STRIDE + kb];

        const uint32_t a_base = smem_addr(xs) +
            ((uint32_t)((lane & 15) * X_STRIDE + (lane >> 4) * 8) * 2u);

        #pragma unroll
        for (int ks = 0; ks < KSTEPS; ks++) {
            const int kl = ks * 16;

            uint32_t a0[4], a1[4];
            {
                uint32_t addr0 = a_base + (uint32_t)(kl * 2);
                asm volatile("ldmatrix.sync.aligned.m8n8.x4.shared.b16 {%0,%1,%2,%3}, [%4];\n"
                             : "=r"(a0[0]), "=r"(a0[1]), "=r"(a0[2]), "=r"(a0[3]) : "r"(addr0));
                uint32_t addr1 = addr0 + (uint32_t)(16 * X_STRIDE * 2);
                asm volatile("ldmatrix.sync.aligned.m8n8.x4.shared.b16 {%0,%1,%2,%3}, [%4];\n"
                             : "=r"(a1[0]), "=r"(a1[1]), "=r"(a1[2]), "=r"(a1[3]) : "r"(addr1));
            }

            int2 w0 = *reinterpret_cast<const int2*>(ws + kl);
            int2 w1 = *reinterpret_cast<const int2*>(ws + kl + 8);
            __half2 b0h = __halves2half2(__int2half_rn(w0.x), __int2half_rn(w0.y));
            __half2 b1h = __halves2half2(__int2half_rn(w1.x), __int2half_rn(w1.y));
            uint32_t b0 = *reinterpret_cast<uint32_t*>(&b0h);
            uint32_t b1 = *reinterpret_cast<uint32_t*>(&b1h);

            asm volatile(
                "mma.sync.aligned.m16n8k16.row.col.f32.f16.f16.f32 "
                "{%0,%1,%2,%3}, {%4,%5,%6,%7}, {%8,%9}, {%0,%1,%2,%3};\n"
                : "+f"(acc[0][0]), "+f"(acc[0][1]), "+f"(acc[0][2]), "+f"(acc[0][3])
                : "r"(a0[0]), "r"(a0[1]), "r"(a0[2]), "r"(a0[3]), "r"(b0), "r"(b1));
            asm volatile(
                "mma.sync.aligned.m16n8k16.row.col.f32.f16.f16.f32 "
                "{%0,%1,%2,%3}, {%4,%5,%6,%7}, {%8,%9}, {%0,%1,%2,%3};\n"
                : "+f"(acc[1][0]), "+f"(acc[1][1]), "+f"(acc[1][2]), "+f"(acc[1][3])
                : "r"(a1[0]), "r"(a1[1]), "r"(a1[2]), "r"(a1[3]), "r"(b0), "r"(b1));
        }

        if (has_next) sts_x(sx[buf ^ 1], tid, xa, xb);   // stage next x tile
        __syncthreads();   // compute on buf done everywhere; sts_x visible; stage reusable
    }

    // Store raw fp32 partials for this split.
    {
        float* pbase = g_part + (size_t)split * MN;
        const int oc = n_base + warp * 8 + (lane & 3) * 2;
        #pragma unroll
        for (int mt = 0; mt < 2; mt++) {
            const int t0 = mt * 16 + (lane >> 2);
            *reinterpret_cast<float2*>(pbase + (size_t)t0 * N_DIM + oc) =
                make_float2(acc[mt][0], acc[mt][1]);
            *reinterpret_cast<float2*>(pbase + (size_t)(t0 + 8) * N_DIM + oc) =
                make_float2(acc[mt][2], acc[mt][3]);
        }
    }

    // Make partials visible, then count arrivals for this n-tile.
    __threadfence();
    __syncthreads();
    if (tid == 0) {
        int old = atomicAdd(&g_cnt[blockIdx.x], 1);
        s_last = ((old & (SPLIT_K - 1)) == (SPLIT_K - 1)) ? 1 : 0;
    }
    __syncthreads();

    // Last-arriving CTA for this n-tile reduces all splits (fixed order ->
    // deterministic) and writes final output with scale/bias + fp16 rounding.
    if (s_last) {
        __threadfence();
        const int row = tid >> 3;                 // 0..31
        const int cg  = n_base + (tid & 7) * 8;   // 8-col group
        const size_t off = (size_t)row * N_DIM + cg;

        float4 p0 = ldg_cg4(g_part + off);
        float4 p1 = ldg_cg4(g_part + off + 4);
        #pragma unroll
        for (int s = 1; s < SPLIT_K; s++) {
            const float* p = g_part + (size_t)s * MN + off;
            float4 q0 = ldg_cg4(p);
            float4 q1 = ldg_cg4(p + 4);
            p0.x += q0.x; p0.y += q0.y; p0.z += q0.z; p0.w += q0.w;
            p1.x += q1.x; p1.y += q1.y; p1.z += q1.z; p1.w += q1.w;
        }

        float4 sc0 = *reinterpret_cast<const float4*>(scales + cg);
        float4 sc1 = *reinterpret_cast<const float4*>(scales + cg + 4);
        float4 bz0 = *reinterpret_cast<const float4*>(bias + cg);
        float4 bz1 = *reinterpret_cast<const float4*>(bias + cg + 4);

        float4 v0, v1;
        v0.x = __half2float(__float2half(p0.x * sc0.x + bz0.x));
        v0.y = __half2float(__float2half(p0.y * sc0.y + bz0.y));
        v0.z = __half2float(__float2half(p0.z * sc0.z + bz0.z));
        v0.w = __half2float(__float2half(p0.w * sc0.w + bz0.w));
        v1.x = __half2float(__float2half(p1.x * sc1.x + bz1.x));
        v1.y = __half2float(__float2half(p1.y * sc1.y + bz1.y));
        v1.z = __half2float(__float2half(p1.z * sc1.z + bz1.z));
        v1.w = __half2float(__float2half(p1.w * sc1.w + bz1.w));

        *reinterpret_cast<float4*>(out + off)     = v0;
        *reinterpret_cast<float4*>(out + off + 4) = v1;
    }
}

extern "C" void kernel_launch(void* const* d_in, const int* in_sizes, int n_in,
                              void* d_out, int out_size)
{
    const float*    x      = (const float*)d_in[0];
    const int32_t*  qw     = (const int32_t*)d_in[1];
    const float*    scales = (const float*)d_in[2];
    const float*    bias   = (const float*)d_in[3];
    float*          out    = (float*)d_out;

    dim3 grid(N_TILES, SPLIT_K);   // (172, 8) = 1376 CTAs
    qlinear_s8_kernel<<<grid, THREADS>>>(qw, x, scales, bias, out);
}

// round 16
// speedup vs baseline: 1.7002x; 1.7002x over previous
#include <cuda_runtime.h>
#include <cuda_fp16.h>
#include <stdint.h>

// Problem constants (fixed shapes from reference)
#define M_DIM 32
#define N_DIM 11008
#define K_DIM 4096

// Harness promotes unsupported dtypes: float16 -> float32, int8 -> int32.
// x fp32 [32,4096], qweight int32 [11008,4096], scales fp32 [11008],
// bias fp32 [11008], out fp32 [32,11008] (values fp16-rounded like reference).

#define N_TILE   64                 // output channels per CTA (11008 = 172 * 64)
#define N_TILES  (N_DIM / N_TILE)   // 172
#define SPLIT_K  4                  // grid (172, 4) = 688 CTAs
#define K_PER_SPLIT (K_DIM / SPLIT_K)      // 1024
#define K_CHUNK  64                 // K elements staged per pipeline stage
#define N_WARPS  8
#define THREADS  (N_WARPS * 32)
#define N_CHUNKS (K_PER_SPLIT / K_CHUNK)   // 16
#define KSTEPS   (K_CHUNK / 16)     // 4 mma k-steps per chunk

#define X_STRIDE 72                 // halves per x row in smem (64 + 8 pad)
#define W_STRIDE 72                 // int32 per w row in smem (64 + 8 pad)

#define MN (M_DIM * N_DIM)          // 352256

// fp32 split-K partials. Static device scratch (no allocation in kernel_launch).
__device__ float g_part[SPLIT_K * MN];   // 5.64 MB

__device__ __forceinline__ uint32_t smem_addr(const void* p) {
    return (uint32_t)__cvta_generic_to_shared(p);
}

// cp.async the weight tile for K-chunk starting at k0 into sw (one commit group).
__device__ __forceinline__ void issue_w(
    const int32_t* __restrict__ qw, int n_base, int32_t* sw, int k0, int tid)
{
    #pragma unroll
    for (int s = 0; s < 4; s++) {
        int seg = tid + s * THREADS;
        int row = seg >> 4;
        int col = seg & 15;
        const int32_t* src = qw + (size_t)(n_base + row) * K_DIM + k0 + col * 4;
        uint32_t dst = smem_addr(sw + row * W_STRIDE + col * 4);
        asm volatile("cp.async.cg.shared.global [%0], [%1], 16;\n" :: "r"(dst), "l"(src));
    }
    asm volatile("cp.async.commit_group;\n");
}

__device__ __forceinline__ void ldg_x(
    const float* __restrict__ x32, int k0, int tid, float4& a, float4& b)
{
    const float* src = x32 + (size_t)(tid >> 3) * K_DIM + k0 + (tid & 7) * 8;
    a = __ldg((const float4*)src);
    b = __ldg((const float4*)(src + 4));
}

__device__ __forceinline__ void sts_x(__half* sx, int tid, float4 a, float4 b)
{
    __half2 h[4];
    h[0] = __halves2half2(__float2half(a.x), __float2half(a.y));
    h[1] = __halves2half2(__float2half(a.z), __float2half(a.w));
    h[2] = __halves2half2(__float2half(b.x), __float2half(b.y));
    h[3] = __halves2half2(__float2half(b.z), __float2half(b.w));
    *reinterpret_cast<uint4*>(sx + (tid >> 3) * X_STRIDE + (tid & 7) * 8) =
        *reinterpret_cast<uint4*>(h);
}

__device__ __forceinline__ float4 ldg_cg4(const float* p) {
    float4 q;
    asm volatile("ld.global.cg.v4.f32 {%0,%1,%2,%3}, [%4];"
                 : "=f"(q.x), "=f"(q.y), "=f"(q.z), "=f"(q.w) : "l"(p));
    return q;
}

__global__ void __launch_bounds__(THREADS, 3)
qlinear_s8_kernel(const int32_t* __restrict__ qw, const float* __restrict__ x32)
{
    __shared__ __align__(16) __half   sx[2][M_DIM * X_STRIDE];   // 2 x 4608 B
    __shared__ __align__(16) int32_t  sw[2][N_TILE * W_STRIDE];  // 2 x 18432 B

    const int tid  = threadIdx.x;
    const int warp = tid >> 5;
    const int lane = tid & 31;
    const int n_base = blockIdx.x * N_TILE;
    const int split  = blockIdx.y;
    const int k_base = split * K_PER_SPLIT;

    float acc[2][4] = {{0.f, 0.f, 0.f, 0.f}, {0.f, 0.f, 0.f, 0.f}};

    // B operand per-thread source: row (n) = warp*8 + lane/4, k offset (lane%4)*2.
    const int o_row = warp * 8 + (lane >> 2);
    const int kb    = (lane & 3) * 2;

    // Prologue: stage chunk 0 (weights via cp.async, x via LDG->cvt->STS).
    issue_w(qw, n_base, sw[0], k_base, tid);
    {
        float4 xa, xb;
        ldg_x(x32, k_base, tid, xa, xb);
        sts_x(sx[0], tid, xa, xb);
    }

    #pragma unroll 1
    for (int ch = 0; ch < N_CHUNKS; ch++) {
        const int buf = ch & 1;
        float4 xa, xb;
        const bool has_next = (ch + 1 < N_CHUNKS);

        if (has_next) {
            issue_w(qw, n_base, sw[buf ^ 1], k_base + (ch + 1) * K_CHUNK, tid);
            ldg_x(x32, k_base + (ch + 1) * K_CHUNK, tid, xa, xb);   // hidden by MMAs
            asm volatile("cp.async.wait_group 1;\n");
        } else {
            asm volatile("cp.async.wait_group 0;\n");
        }
        __syncthreads();   // (A) chunk `ch` tiles ready for everyone

        const __half*   xs = sx[buf];
        const int32_t*  ws = &sw[buf][o_row * W_STRIDE + kb];

        const uint32_t a_base = smem_addr(xs) +
            ((uint32_t)((lane & 15) * X_STRIDE + (lane >> 4) * 8) * 2u);

        #pragma unroll
        for (int ks = 0; ks < KSTEPS; ks++) {
            const int kl = ks * 16;

            uint32_t a0[4], a1[4];
            {
                uint32_t addr0 = a_base + (uint32_t)(kl * 2);
                asm volatile("ldmatrix.sync.aligned.m8n8.x4.shared.b16 {%0,%1,%2,%3}, [%4];\n"
                             : "=r"(a0[0]), "=r"(a0[1]), "=r"(a0[2]), "=r"(a0[3]) : "r"(addr0));
                uint32_t addr1 = addr0 + (uint32_t)(16 * X_STRIDE * 2);
                asm volatile("ldmatrix.sync.aligned.m8n8.x4.shared.b16 {%0,%1,%2,%3}, [%4];\n"
                             : "=r"(a1[0]), "=r"(a1[1]), "=r"(a1[2]), "=r"(a1[3]) : "r"(addr1));
            }

            int2 w0 = *reinterpret_cast<const int2*>(ws + kl);
            int2 w1 = *reinterpret_cast<const int2*>(ws + kl + 8);
            __half2 b0h = __halves2half2(__int2half_rn(w0.x), __int2half_rn(w0.y));
            __half2 b1h = __halves2half2(__int2half_rn(w1.x), __int2half_rn(w1.y));
            uint32_t b0 = *reinterpret_cast<uint32_t*>(&b0h);
            uint32_t b1 = *reinterpret_cast<uint32_t*>(&b1h);

            asm volatile(
                "mma.sync.aligned.m16n8k16.row.col.f32.f16.f16.f32 "
                "{%0,%1,%2,%3}, {%4,%5,%6,%7}, {%8,%9}, {%0,%1,%2,%3};\n"
                : "+f"(acc[0][0]), "+f"(acc[0][1]), "+f"(acc[0][2]), "+f"(acc[0][3])
                : "r"(a0[0]), "r"(a0[1]), "r"(a0[2]), "r"(a0[3]), "r"(b0), "r"(b1));
            asm volatile(
                "mma.sync.aligned.m16n8k16.row.col.f32.f16.f16.f32 "
                "{%0,%1,%2,%3}, {%4,%5,%6,%7}, {%8,%9}, {%0,%1,%2,%3};\n"
                : "+f"(acc[1][0]), "+f"(acc[1][1]), "+f"(acc[1][2]), "+f"(acc[1][3])
                : "r"(a1[0]), "r"(a1[1]), "r"(a1[2]), "r"(a1[3]), "r"(b0), "r"(b1));
        }

        if (has_next) sts_x(sx[buf ^ 1], tid, xa, xb);   // stage next x tile
        __syncthreads();   // (B) compute on buf done; sts_x visible before next read
    }

    // Store raw fp32 partials (scale/bias applied in combine kernel).
    float* pbase = g_part + (size_t)split * MN;
    const int oc = n_base + warp * 8 + (lane & 3) * 2;

    #pragma unroll
    for (int mt = 0; mt < 2; mt++) {
        const int t0 = mt * 16 + (lane >> 2);
        *reinterpret_cast<float2*>(pbase + (size_t)t0 * N_DIM + oc) =
            make_float2(acc[mt][0], acc[mt][1]);
        *reinterpret_cast<float2*>(pbase + (size_t)(t0 + 8) * N_DIM + oc) =
            make_float2(acc[mt][2], acc[mt][3]);
    }
}

// Combine: out[t,o] = fp16_round((sum_s part[s,t,o]) * scale[o] + bias[o]) as fp32.
// 8 contiguous elements per thread -> 8 independent v4 loads in flight (MLP 8).
__global__ void __launch_bounds__(THREADS)
combine_kernel(const float* __restrict__ scales,
               const float* __restrict__ bias,
               float* __restrict__ out)
{
    const int i = (blockIdx.x * THREADS + threadIdx.x) * 8;   // elem t*N+o, o % 8 == 0
    const int o = i % N_DIM;

    // Issue all SPLIT_K*2 loads up front (independent).
    float4 a[SPLIT_K], b[SPLIT_K];
    #pragma unroll
    for (int s = 0; s < SPLIT_K; s++) {
        const float* p = g_part + (size_t)s * MN + i;
        a[s] = ldg_cg4(p);
        b[s] = ldg_cg4(p + 4);
    }
    float4 p0 = a[0], p1 = b[0];
    #pragma unroll
    for (int s = 1; s < SPLIT_K; s++) {
        p0.x += a[s].x; p0.y += a[s].y; p0.z += a[s].z; p0.w += a[s].w;
        p1.x += b[s].x; p1.y += b[s].y; p1.z += b[s].z; p1.w += b[s].w;
    }

    float4 sc0 = *reinterpret_cast<const float4*>(scales + o);
    float4 sc1 = *reinterpret_cast<const float4*>(scales + o + 4);
    float4 bz0 = *reinterpret_cast<const float4*>(bias + o);
    float4 bz1 = *reinterpret_cast<const float4*>(bias + o + 4);

    float4 v0, v1;
    v0.x = __half2float(__float2half(p0.x * sc0.x + bz0.x));
    v0.y = __half2float(__float2half(p0.y * sc0.y + bz0.y));
    v0.z = __half2float(__float2half(p0.z * sc0.z + bz0.z));
    v0.w = __half2float(__float2half(p0.w * sc0.w + bz0.w));
    v1.x = __half2float(__float2half(p1.x * sc1.x + bz1.x));
    v1.y = __half2float(__float2half(p1.y * sc1.y + bz1.y));
    v1.z = __half2float(__float2half(p1.z * sc1.z + bz1.z));
    v1.w = __half2float(__float2half(p1.w * sc1.w + bz1.w));

    *reinterpret_cast<float4*>(out + i)     = v0;
    *reinterpret_cast<float4*>(out + i + 4) = v1;
}

extern "C" void kernel_launch(void* const* d_in, const int* in_sizes, int n_in,
                              void* d_out, int out_size)
{
    const float*    x      = (const float*)d_in[0];
    const int32_t*  qw     = (const int32_t*)d_in[1];
    const float*    scales = (const float*)d_in[2];
    const float*    bias   = (const float*)d_in[3];
    float*          out    = (float*)d_out;

    dim3 grid(N_TILES, SPLIT_K);   // (172, 4) = 688 CTAs
    qlinear_s8_kernel<<<grid, THREADS>>>(qw, x);

    combine_kernel<<<MN / (THREADS * 8), THREADS>>>(scales, bias, out);  // 172 blocks
}

// round 17
// speedup vs baseline: 1.9276x; 1.1338x over previous
#include <cuda_runtime.h>
#include <cuda_fp16.h>
#include <stdint.h>

// Problem constants (fixed shapes from reference)
#define M_DIM 32
#define N_DIM 11008
#define K_DIM 4096

// Harness promotes unsupported dtypes: float16 -> float32, int8 -> int32.
// x fp32 [32,4096], qweight int32 [11008,4096], scales fp32 [11008],
// bias fp32 [11008], out fp32 [32,11008] (values fp16-rounded like reference).

#define N_TILE   64                 // output channels per CTA (11008 = 172 * 64)
#define N_TILES  (N_DIM / N_TILE)   // 172
#define SPLIT_K  4                  // grid (172, 4) = 688 CTAs
#define K_PER_SPLIT (K_DIM / SPLIT_K)      // 1024
#define K_CHUNK  64                 // K elements staged per pipeline stage
#define N_WARPS  8
#define THREADS  (N_WARPS * 32)
#define N_CHUNKS (K_PER_SPLIT / K_CHUNK)   // 16
#define KSTEPS   (K_CHUNK / 16)     // 4 mma k-steps per chunk

#define X_STRIDE 72                 // halves per x row in smem (64 + 8 pad)
#define W_STRIDE 72                 // int32 per w row in smem (64 + 8 pad)

#define MN (M_DIM * N_DIM)          // 352256

// fp32 split-K partials. Static device scratch (no allocation in kernel_launch).
__device__ float g_part[SPLIT_K * MN];   // 5.64 MB

__device__ __forceinline__ uint32_t smem_addr(const void* p) {
    return (uint32_t)__cvta_generic_to_shared(p);
}

// cp.async the weight tile for K-chunk starting at k0 into sw (one commit group).
// .L2::256B prefetches the adjacent 256B (next chunk's row segment) into L2.
__device__ __forceinline__ void issue_w(
    const int32_t* __restrict__ qw, int n_base, int32_t* sw, int k0, int tid)
{
    #pragma unroll
    for (int s = 0; s < 4; s++) {
        int seg = tid + s * THREADS;
        int row = seg >> 4;
        int col = seg & 15;
        const int32_t* src = qw + (size_t)(n_base + row) * K_DIM + k0 + col * 4;
        uint32_t dst = smem_addr(sw + row * W_STRIDE + col * 4);
        asm volatile("cp.async.cg.shared.global.L2::256B [%0], [%1], 16;\n"
                     :: "r"(dst), "l"(src));
    }
    asm volatile("cp.async.commit_group;\n");
}

__device__ __forceinline__ void ldg_x(
    const float* __restrict__ x32, int k0, int tid, float4& a, float4& b)
{
    const float* src = x32 + (size_t)(tid >> 3) * K_DIM + k0 + (tid & 7) * 8;
    a = __ldg((const float4*)src);
    b = __ldg((const float4*)(src + 4));
}

__device__ __forceinline__ void sts_x(__half* sx, int tid, float4 a, float4 b)
{
    __half2 h[4];
    h[0] = __halves2half2(__float2half(a.x), __float2half(a.y));
    h[1] = __halves2half2(__float2half(a.z), __float2half(a.w));
    h[2] = __halves2half2(__float2half(b.x), __float2half(b.y));
    h[3] = __halves2half2(__float2half(b.z), __float2half(b.w));
    *reinterpret_cast<uint4*>(sx + (tid >> 3) * X_STRIDE + (tid & 7) * 8) =
        *reinterpret_cast<uint4*>(h);
}

__device__ __forceinline__ float4 ldg_cg4(const float* p) {
    float4 q;
    asm volatile("ld.global.cg.v4.f32 {%0,%1,%2,%3}, [%4];"
                 : "=f"(q.x), "=f"(q.y), "=f"(q.z), "=f"(q.w) : "l"(p));
    return q;
}

__global__ void __launch_bounds__(THREADS, 3)
qlinear_s8_kernel(const int32_t* __restrict__ qw, const float* __restrict__ x32)
{
    __shared__ __align__(16) __half   sx[2][M_DIM * X_STRIDE];   // 2 x 4608 B
    __shared__ __align__(16) int32_t  sw[2][N_TILE * W_STRIDE];  // 2 x 18432 B

    const int tid  = threadIdx.x;
    const int warp = tid >> 5;
    const int lane = tid & 31;
    const int n_base = blockIdx.x * N_TILE;
    const int split  = blockIdx.y;
    const int k_base = split * K_PER_SPLIT;

    float acc[2][4] = {{0.f, 0.f, 0.f, 0.f}, {0.f, 0.f, 0.f, 0.f}};

    // B operand per-thread source: row (n) = warp*8 + lane/4, k offset (lane%4)*2.
    const int o_row = warp * 8 + (lane >> 2);
    const int kb    = (lane & 3) * 2;

    // Prologue: stage chunk 0 (weights via cp.async, x via LDG->cvt->STS).
    issue_w(qw, n_base, sw[0], k_base, tid);
    {
        float4 xa, xb;
        ldg_x(x32, k_base, tid, xa, xb);
        sts_x(sx[0], tid, xa, xb);
    }

    // Fully unrolled (N_CHUNKS compile-time): buf constant-folds, no loop branch.
    #pragma unroll
    for (int ch = 0; ch < N_CHUNKS; ch++) {
        const int buf = ch & 1;
        float4 xa, xb;
        const bool has_next = (ch + 1 < N_CHUNKS);

        if (has_next) {
            issue_w(qw, n_base, sw[buf ^ 1], k_base + (ch + 1) * K_CHUNK, tid);
            ldg_x(x32, k_base + (ch + 1) * K_CHUNK, tid, xa, xb);   // hidden by MMAs
            asm volatile("cp.async.wait_group 1;\n");
        } else {
            asm volatile("cp.async.wait_group 0;\n");
        }
        __syncthreads();   // (A) chunk `ch` tiles ready for everyone

        const __half*   xs = sx[buf];
        const int32_t*  ws = &sw[buf][o_row * W_STRIDE + kb];

        const uint32_t a_base = smem_addr(xs) +
            ((uint32_t)((lane & 15) * X_STRIDE + (lane >> 4) * 8) * 2u);

        #pragma unroll
        for (int ks = 0; ks < KSTEPS; ks++) {
            const int kl = ks * 16;

            uint32_t a0[4], a1[4];
            {
                uint32_t addr0 = a_base + (uint32_t)(kl * 2);
                asm volatile("ldmatrix.sync.aligned.m8n8.x4.shared.b16 {%0,%1,%2,%3}, [%4];\n"
                             : "=r"(a0[0]), "=r"(a0[1]), "=r"(a0[2]), "=r"(a0[3]) : "r"(addr0));
                uint32_t addr1 = addr0 + (uint32_t)(16 * X_STRIDE * 2);
                asm volatile("ldmatrix.sync.aligned.m8n8.x4.shared.b16 {%0,%1,%2,%3}, [%4];\n"
                             : "=r"(a1[0]), "=r"(a1[1]), "=r"(a1[2]), "=r"(a1[3]) : "r"(addr1));
            }

            int2 w0 = *reinterpret_cast<const int2*>(ws + kl);
            int2 w1 = *reinterpret_cast<const int2*>(ws + kl + 8);
            __half2 b0h = __halves2half2(__int2half_rn(w0.x), __int2half_rn(w0.y));
            __half2 b1h = __halves2half2(__int2half_rn(w1.x), __int2half_rn(w1.y));
            uint32_t b0 = *reinterpret_cast<uint32_t*>(&b0h);
            uint32_t b1 = *reinterpret_cast<uint32_t*>(&b1h);

            asm volatile(
                "mma.sync.aligned.m16n8k16.row.col.f32.f16.f16.f32 "
                "{%0,%1,%2,%3}, {%4,%5,%6,%7}, {%8,%9}, {%0,%1,%2,%3};\n"
                : "+f"(acc[0][0]), "+f"(acc[0][1]), "+f"(acc[0][2]), "+f"(acc[0][3])
                : "r"(a0[0]), "r"(a0[1]), "r"(a0[2]), "r"(a0[3]), "r"(b0), "r"(b1));
            asm volatile(
                "mma.sync.aligned.m16n8k16.row.col.f32.f16.f16.f32 "
                "{%0,%1,%2,%3}, {%4,%5,%6,%7}, {%8,%9}, {%0,%1,%2,%3};\n"
                : "+f"(acc[1][0]), "+f"(acc[1][1]), "+f"(acc[1][2]), "+f"(acc[1][3])
                : "r"(a1[0]), "r"(a1[1]), "r"(a1[2]), "r"(a1[3]), "r"(b0), "r"(b1));
        }

        if (has_next) sts_x(sx[buf ^ 1], tid, xa, xb);   // stage next x tile
        __syncthreads();   // (B) compute on buf done; sts_x visible before next read
    }

    // Store raw fp32 partials (scale/bias applied in combine kernel).
    float* pbase = g_part + (size_t)split * MN;
    const int oc = n_base + warp * 8 + (lane & 3) * 2;

    #pragma unroll
    for (int mt = 0; mt < 2; mt++) {
        const int t0 = mt * 16 + (lane >> 2);
        *reinterpret_cast<float2*>(pbase + (size_t)t0 * N_DIM + oc) =
            make_float2(acc[mt][0], acc[mt][1]);
        *reinterpret_cast<float2*>(pbase + (size_t)(t0 + 8) * N_DIM + oc) =
            make_float2(acc[mt][2], acc[mt][3]);
    }
}

// Combine: out[t,o] = fp16_round((sum_s part[s,t,o]) * scale[o] + bias[o]) as fp32.
__global__ void __launch_bounds__(THREADS)
combine_kernel(const float* __restrict__ scales,
               const float* __restrict__ bias,
               float* __restrict__ out)
{
    const int i = (blockIdx.x * THREADS + threadIdx.x) * 4;   // element t*N+o, o % 4 == 0
    const int o = i % N_DIM;

    // Issue all SPLIT_K loads up front (independent, MLP 4).
    float4 a[SPLIT_K];
    #pragma unroll
    for (int s = 0; s < SPLIT_K; s++)
        a[s] = ldg_cg4(g_part + (size_t)s * MN + i);

    float4 p = a[0];
    #pragma unroll
    for (int s = 1; s < SPLIT_K; s++) {
        p.x += a[s].x; p.y += a[s].y; p.z += a[s].z; p.w += a[s].w;
    }

    float4 sc = *reinterpret_cast<const float4*>(scales + o);
    float4 bz = *reinterpret_cast<const float4*>(bias + o);

    float4 v;
    v.x = __half2float(__float2half(p.x * sc.x + bz.x));
    v.y = __half2float(__float2half(p.y * sc.y + bz.y));
    v.z = __half2float(__float2half(p.z * sc.z + bz.z));
    v.w = __half2float(__float2half(p.w * sc.w + bz.w));
    *reinterpret_cast<float4*>(out + i) = v;
}

extern "C" void kernel_launch(void* const* d_in, const int* in_sizes, int n_in,
                              void* d_out, int out_size)
{
    const float*    x      = (const float*)d_in[0];
    const int32_t*  qw     = (const int32_t*)d_in[1];
    const float*    scales = (const float*)d_in[2];
    const float*    bias   = (const float*)d_in[3];
    float*          out    = (float*)d_out;

    dim3 grid(N_TILES, SPLIT_K);   // (172, 4) = 688 CTAs
    qlinear_s8_kernel<<<grid, THREADS>>>(qw, x);

    combine_kernel<<<MN / (THREADS * 4), THREADS>>>(scales, bias, out);  // 344 blocks
}